// round 14
// baseline (speedup 1.0000x reference)
#include <cuda_runtime.h>
#include <cuda_fp16.h>
#include <cstdint>

// Shapes (specialized)
#define B_SZ   1024
#define I_SZ   64
#define U_SZ   1024
#define T_SZ   256
#define KC     64          // K per chunk
#define NCHK   17          // (64+1024)/64
#define BM     128
#define BN     256         // 64 units x 4 gates (col = 4*u_local + gate)
#define UN     64
#define NTHR   512         // 16 warps: 4 in M x 4 in N, warp tile 32x64

// fp16 fragment-major chunk images (m16n8k16):
#define A_CH_U32  4096
#define W_CH_U32  8192
#define A_CH_HALF (A_CH_U32 * 2)
#define W_CH_HALF (W_CH_U32 * 2)
#define A_BYTES   (A_CH_U32 * 4)               // 16384
#define W_BYTES   (W_CH_U32 * 4)               // 32768
#define STAGE_U32 (A_CH_U32 + W_CH_U32)        // 12288 u32 = 48KB
#define STAGE_BYTES (STAGE_U32 * 4)
#define NSTAGE    4
#define SMEM_BYTES (NSTAGE * STAGE_BYTES)      // 192KB dynamic

// ---------------- device state ----------------
__device__ float  g_h[2][B_SZ * U_SZ];                           // linear h (dense head)
__device__ float  g_c[B_SZ * U_SZ];
__device__ __align__(16) __half g_hFrag[2][8 * 16 * A_CH_HALF];  // [par][mtile][ch-1][frag]
__device__ __align__(16) __half g_xFrag[8 * 256 * A_CH_HALF];    // [mtile][t][frag]
__device__ __align__(16) __half g_pFrag[8 * A_CH_HALF];          // [mtile][frag]
__device__ __align__(16) __half g_WFrag[NCHK * 16 * W_CH_HALF];  // [kc][utile][frag]
__device__ float4 g_bias4[U_SZ];                                 // (bi,bf,bg,bo)

// ---------------- helpers ----------------
__device__ __forceinline__ void mma_f16(float (&d)[4], const uint32_t (&a)[4],
                                        uint32_t b0, uint32_t b1) {
    asm volatile(
        "mma.sync.aligned.m16n8k16.row.col.f32.f16.f16.f32 "
        "{%0,%1,%2,%3}, {%4,%5,%6,%7}, {%8,%9}, {%0,%1,%2,%3};\n"
        : "+f"(d[0]), "+f"(d[1]), "+f"(d[2]), "+f"(d[3])
        : "r"(a[0]), "r"(a[1]), "r"(a[2]), "r"(a[3]), "r"(b0), "r"(b1));
}
// fast gates: __expf-based (rel err ~1e-6, overflow-safe forms)
__device__ __forceinline__ float fsigm(float x) {
    return 1.0f / (1.0f + __expf(-x));
}
__device__ __forceinline__ float ftanh(float x) {
    float e = __expf(2.0f * x);                    // e->inf: t->1 ; e->0: t->-1
    return 1.0f - __fdividef(2.0f, e + 1.0f);
}

__device__ __forceinline__ void mbar_init(uint32_t mbar, uint32_t count) {
    asm volatile("mbarrier.init.shared.b64 [%0], %1;" :: "r"(mbar), "r"(count) : "memory");
}
__device__ __forceinline__ void mbar_expect_tx(uint32_t mbar, uint32_t bytes) {
    asm volatile("mbarrier.arrive.expect_tx.shared.b64 _, [%0], %1;"
                 :: "r"(mbar), "r"(bytes) : "memory");
}
__device__ __forceinline__ void mbar_wait(uint32_t mbar, uint32_t parity) {
    asm volatile(
        "{\n\t.reg .pred P;\n\t"
        "W%=:\n\t"
        "mbarrier.try_wait.parity.acquire.cta.shared::cta.b64 P, [%0], %1, 0x989680;\n\t"
        "@P bra.uni D%=;\n\t"
        "bra.uni W%=;\n\t"
        "D%=:\n\t}"
        :: "r"(mbar), "r"(parity) : "memory");
}
// 1-D bulk async copy global->shared, completion via mbarrier tx-bytes (sm_90+)
__device__ __forceinline__ void bulk_cp(uint32_t dst, const void* src, uint32_t bytes,
                                        uint32_t mbar) {
    asm volatile(
        "cp.async.bulk.shared::cluster.global.mbarrier::complete_tx::bytes [%0], [%1], %2, [%3];"
        :: "r"(dst), "l"(src), "r"(bytes), "r"(mbar) : "memory");
}

// half index of A-side element (m in [0,128), k in [0,64)) within a chunk image
__device__ __forceinline__ int a_frag_hidx(int m, int k) {
    int ks = k >> 4, kin = k & 15;
    int khi = kin >> 3, tigk = (kin & 7) >> 1, hsel = kin & 1;
    int m16 = m >> 4, r16 = m & 15, gid = r16 & 7, rhi = r16 >> 3;
    int lane = gid * 4 + tigk;
    int q = khi * 2 + rhi;
    return ((((ks * 8 + m16) * 32) + lane) * 4 + q) * 2 + hsel;
}

// ---------------- prep kernels (once per launch) ----------------
__global__ void init_state_kernel() {
    int i = blockIdx.x * blockDim.x + threadIdx.x;
    if (i < B_SZ * U_SZ) g_c[i] = 0.0f;
    if (i < 8 * 16 * A_CH_HALF) g_hFrag[0][i] = __float2half(0.0f);
}

__global__ void prep_x_kernel(const float* __restrict__ x) {
    int i = blockIdx.x * blockDim.x + threadIdx.x;   // over B*T*I
    if (i >= B_SZ * T_SZ * I_SZ) return;
    int col = i & 63, t = (i >> 6) & 255, row = i >> 14;
    int mtile = row >> 7, m = row & 127;
    g_xFrag[((size_t)mtile * 256 + t) * A_CH_HALF + a_frag_hidx(m, col)] = __float2half_rn(x[i]);
}

__global__ void prep_w_kernel(const float* __restrict__ Wk, const float* __restrict__ Wr) {
    int i = blockIdx.x * blockDim.x + threadIdx.x;   // over NCHK*16*W_CH_HALF
    if (i >= NCHK * 16 * W_CH_HALF) return;
    int hsel  = i & 1;
    int jp    = (i >> 1) & 3;
    int lane  = (i >> 3) & 31;
    int nbp   = (i >> 8) & 15;
    int ks    = (i >> 12) & 3;
    int utile = (i >> 14) & 15;
    int kc    = i >> 18;
    int gid = lane >> 2, tigk = lane & 3;
    int n8 = nbp * 2 + (jp >> 1);
    int bhi = jp & 1;
    int n_local = n8 * 8 + gid;                        // 0..255 = 4*u_local + gate
    int ul = n_local >> 2, gate = n_local & 3;
    int colW = gate * U_SZ + utile * UN + ul;
    int kg = kc * KC + ks * 16 + bhi * 8 + tigk * 2 + hsel;
    float v = (kg < I_SZ) ? Wk[(size_t)kg * 4096 + colW]
                          : Wr[(size_t)(kg - I_SZ) * 4096 + colW];
    g_WFrag[i] = __float2half_rn(v);
}

__global__ void prep_bias_kernel(const float* __restrict__ b) {
    int u = blockIdx.x * blockDim.x + threadIdx.x;
    if (u < U_SZ)
        g_bias4[u] = make_float4(b[u], b[U_SZ + u], b[2 * U_SZ + u], b[3 * U_SZ + u]);
}

// ---------------- LSTM step (TMA bulk copies, mbarrier pipeline) ----------------
__global__ __launch_bounds__(NTHR, 1)
void lstm_step_kernel(int t, int par, int use_pred) {
    extern __shared__ uint32_t smu[];
    __shared__ __align__(8) uint64_t mbars[NSTAGE];

    uint32_t smb;
    asm("{ .reg .u64 t; cvta.to.shared.u64 t, %1; cvt.u32.u64 %0, t; }" : "=r"(smb) : "l"(smu));
    uint32_t mb0;
    asm("{ .reg .u64 t; cvta.to.shared.u64 t, %1; cvt.u32.u64 %0, t; }" : "=r"(mb0) : "l"(mbars));

    const int tid  = threadIdx.x;
    const int lane = tid & 31;
    const int wid  = tid >> 5;        // 0..15
    const int gid  = lane >> 2;
    const int tig  = lane & 3;

    const int utile = blockIdx.x & 15;
    const int mtile = blockIdx.x >> 4;
    const int u0 = utile * UN;
    const int m0 = mtile * BM;

    const int wmi = wid >> 2;         // M warp 0..3
    const int wni = wid & 3;          // N warp 0..3
    const int wm0 = wmi * 32;
    const int wn0 = wni * 64;
    const int m16b = wmi * 2;         // A m16 base (+mt in 0..1)
    const int nbpb = wni * 4;         // W nbp base (+ntp in 0..3)

    if (tid == 0) {
#pragma unroll
        for (int s = 0; s < NSTAGE; s++) mbar_init(mb0 + s * 8, 1);
    }
    __syncthreads();

    auto issue = [&](int ch) {
        uint32_t mbar = mb0 + (uint32_t)(ch & 3) * 8u;
        uint32_t stg  = smb + (uint32_t)(ch & 3) * STAGE_BYTES;
        const void* a;
        if (ch == 0) {
            a = use_pred ? (const void*)(g_pFrag + (size_t)mtile * A_CH_HALF)
                         : (const void*)(g_xFrag + ((size_t)mtile * 256 + t) * A_CH_HALF);
        } else {
            a = (const void*)(g_hFrag[par] + ((size_t)mtile * 16 + (ch - 1)) * A_CH_HALF);
        }
        const void* w = (const void*)(g_WFrag + ((size_t)ch * 16 + utile) * W_CH_HALF);
        mbar_expect_tx(mbar, STAGE_BYTES);
        bulk_cp(stg, a, A_BYTES, mbar);
        bulk_cp(stg + A_BYTES, w, W_BYTES, mbar);
    };

    float acc[2][8][4];
#pragma unroll
    for (int mt = 0; mt < 2; mt++)
#pragma unroll
        for (int nt = 0; nt < 8; nt++)
#pragma unroll
            for (int q = 0; q < 4; q++) acc[mt][nt][q] = 0.0f;

    if (tid == 0) { issue(0); issue(1); issue(2); }

    for (int ch = 0; ch < NCHK; ch++) {
        mbar_wait(mb0 + (uint32_t)(ch & 3) * 8u, (uint32_t)((ch >> 2) & 1));
        __syncthreads();
        if (tid == 0 && ch + 3 < NCHK) issue(ch + 3);

        const uint32_t* as = smu + (ch & 3) * STAGE_U32;
        const uint32_t* ws = as + A_CH_U32;

#pragma unroll
        for (int ks = 0; ks < 4; ks++) {
            uint4 a_f[2], b_f[4];
#pragma unroll
            for (int mt = 0; mt < 2; mt++)
                a_f[mt] = *(const uint4*)(as + (((ks * 8 + m16b + mt) * 32) + lane) * 4);
#pragma unroll
            for (int ntp = 0; ntp < 4; ntp++)
                b_f[ntp] = *(const uint4*)(ws + (((ks * 16 + nbpb + ntp) * 32) + lane) * 4);

#pragma unroll
            for (int ntp = 0; ntp < 4; ntp++) {
#pragma unroll
                for (int mt = 0; mt < 2; mt++) {
                    uint32_t af[4] = { a_f[mt].x, a_f[mt].y, a_f[mt].z, a_f[mt].w };
                    mma_f16(acc[mt][2 * ntp],     af, b_f[ntp].x, b_f[ntp].y);
                    mma_f16(acc[mt][2 * ntp + 1], af, b_f[ntp].z, b_f[ntp].w);
                }
            }
        }
    }

    // ---- epilogue: dedup (pg=0 -> row r1, pg=1 -> row r1+8), fast gates, bias4 ----
    const int pg = tig & 1;
    float*  hl = g_h[par ^ 1];
    __half* hf = g_hFrag[par ^ 1] + ((size_t)mtile * 16 + utile) * A_CH_HALF;
#pragma unroll
    for (int mt = 0; mt < 2; mt++) {
        const int r1 = m0 + wm0 + mt * 16 + gid;
        const int m16 = m16b + mt;
#pragma unroll
        for (int nt = 0; nt < 8; nt++) {
            float c0 = acc[mt][nt][0], c1 = acc[mt][nt][1];
            float c2 = acc[mt][nt][2], c3 = acc[mt][nt][3];
            float s0 = __shfl_xor_sync(0xffffffffu, c0, 1);
            float s1 = __shfl_xor_sync(0xffffffffu, c1, 1);
            float s2 = __shfl_xor_sync(0xffffffffu, c2, 1);
            float s3 = __shfl_xor_sync(0xffffffffu, c3, 1);

            const int col  = wn0 + nt * 8 + 2 * tig;
            const int unit = u0 + (col >> 2);
            const float4 b4 = __ldg(&g_bias4[unit]);

            // pg=0: row r1, (i,f)=own c0,c1; (g,o)=partner (=s0,s1)
            // pg=1: row r1+8, (i,f)=partner (=s2,s3); (g,o)=own c2,c3
            const float zi = (pg ? s2 : c0) + b4.x;
            const float zf = (pg ? s3 : c1) + b4.y;
            const float zg = (pg ? c2 : s0) + b4.z;
            const float zo = (pg ? c3 : s1) + b4.w;

            const int row = pg ? (r1 + 8) : r1;
            const int idx = row * U_SZ + unit;
            float cold = g_c[idx];
            float cn = fsigm(zf) * cold + fsigm(zi) * ftanh(zg);
            float hv = fsigm(zo) * ftanh(cn);
            g_c[idx] = cn;
            hl[idx] = hv;

            const int ul2  = unit & 63;
            const int ks2  = ul2 >> 4, kin = ul2 & 15;
            const int khi2 = kin >> 3, tig2 = (kin & 7) >> 1, hsel = kin & 1;
            const int lane2 = gid * 4 + tig2;
            const int q = khi2 * 2 + pg;
            hf[((((ks2 * 8 + m16) * 32) + lane2) * 4 + q) * 2 + hsel] = __float2half_rn(hv);
        }
    }
}

// ---------------- dense head ----------------
__global__ __launch_bounds__(256)
void dense_head_kernel(int par, const float* __restrict__ Wd, const float* __restrict__ bd,
                       const int* __restrict__ oidx, int n_idx,
                       float* __restrict__ out, int s, int S) {
    __shared__ float hs[8 * U_SZ];
    const int tid = threadIdx.x;
    const int r0 = blockIdx.x * 8;
    const float* h = g_h[par];
    for (int i = tid; i < 8 * U_SZ; i += 256)
        hs[i] = h[(size_t)(r0 + (i >> 10)) * U_SZ + (i & 1023)];
    __syncthreads();

    const int icol = tid & 63;
    const int rr = tid >> 6;
#pragma unroll
    for (int rp = 0; rp < 2; rp++) {
        const int r = rr + rp * 4;
        const float* hrow = hs + r * U_SZ;
        float a0 = 0.f, a1 = 0.f, a2 = 0.f, a3 = 0.f;
#pragma unroll 4
        for (int u = 0; u < U_SZ; u += 4) {
            a0 += hrow[u]     * __ldg(Wd + (size_t)u * I_SZ + icol);
            a1 += hrow[u + 1] * __ldg(Wd + (size_t)(u + 1) * I_SZ + icol);
            a2 += hrow[u + 2] * __ldg(Wd + (size_t)(u + 2) * I_SZ + icol);
            a3 += hrow[u + 3] * __ldg(Wd + (size_t)(u + 3) * I_SZ + icol);
        }
        float acc = __ldg(bd + icol) + (a0 + a1) + (a2 + a3);
        const int gb = r0 + r;
        int mtile = gb >> 7, m = gb & 127;
        g_pFrag[(size_t)mtile * A_CH_HALF + a_frag_hidx(m, icol)] = __float2half_rn(acc);
        for (int j = 0; j < n_idx; j++)
            if (__ldg(oidx + j) == icol)
                out[(size_t)gb * S * n_idx + s * n_idx + j] = acc;
    }
}

// ---------------- launch ----------------
extern "C" void kernel_launch(void* const* d_in, const int* in_sizes, int n_in,
                              void* d_out, int out_size) {
    const float* inputs = (const float*)d_in[0];
    const float* Wk     = (const float*)d_in[1];
    const float* Wr     = (const float*)d_in[2];
    const float* bias   = (const float*)d_in[3];
    const float* Wd     = (const float*)d_in[4];
    const float* bd     = (const float*)d_in[5];
    const int*   oidx   = (const int*)d_in[6];
    float*       out    = (float*)d_out;

    const int T     = in_sizes[0] / (B_SZ * I_SZ);   // 256
    const int n_idx = in_sizes[6];                   // 2
    const int S     = out_size / (B_SZ * n_idx);     // 64

    cudaFuncSetAttribute(lstm_step_kernel,
                         cudaFuncAttributeMaxDynamicSharedMemorySize, SMEM_BYTES);

    init_state_kernel<<<(B_SZ * U_SZ + 255) / 256, 256>>>();
    prep_x_kernel<<<(B_SZ * T_SZ * I_SZ + 255) / 256, 256>>>(inputs);
    prep_w_kernel<<<(NCHK * 16 * W_CH_HALF + 255) / 256, 256>>>(Wk, Wr);
    prep_bias_kernel<<<(U_SZ + 255) / 256, 256>>>(bias);

    int par = 0;
    for (int t = 0; t < T; t++) {
        lstm_step_kernel<<<128, NTHR, SMEM_BYTES>>>(t, par, 0);
        par ^= 1;
    }
    dense_head_kernel<<<128, 256>>>(par, Wd, bd, oidx, n_idx, out, 0, S);
    for (int s = 1; s < S; s++) {
        lstm_step_kernel<<<128, NTHR, SMEM_BYTES>>>(0, par, 1);
        par ^= 1;
        dense_head_kernel<<<128, 256>>>(par, Wd, bd, oidx, n_idx, out, s, S);
    }
}

// round 15
// speedup vs baseline: 1.2494x; 1.2494x over previous
#include <cuda_runtime.h>
#include <cuda_fp16.h>
#include <cstdint>

// Shapes (specialized)
#define B_SZ   1024
#define I_SZ   64
#define U_SZ   1024
#define T_SZ   256
#define KC     64          // K per chunk
#define NCHK   17          // (64+1024)/64
#define BM     128
#define BN     256         // 64 units x 4 gates (col = 4*u_local + gate)
#define UN     64
#define NTHR   512         // 16 warps: 4 in M x 4 in N, warp tile 32x64

// fp16 fragment-major chunk images (m16n8k16):
#define A_CH_U32  4096
#define W_CH_U32  8192
#define A_CH_HALF (A_CH_U32 * 2)
#define W_CH_HALF (W_CH_U32 * 2)
#define A_BYTES   (A_CH_U32 * 4)               // 16384
#define W_BYTES   (W_CH_U32 * 4)               // 32768
#define STAGE_U32 (A_CH_U32 + W_CH_U32)        // 12288 u32 = 48KB
#define STAGE_BYTES (STAGE_U32 * 4)
#define NSTAGE    4
#define SMEM_BYTES (NSTAGE * STAGE_BYTES)      // 192KB dynamic

// ---------------- device state ----------------
__device__ float  g_h[2][B_SZ * U_SZ];                           // linear h (dense head)
__device__ float  g_c[B_SZ * U_SZ];
__device__ __align__(16) __half g_hFrag[2][8 * 16 * A_CH_HALF];  // [par][mtile][ch-1][frag]
__device__ __align__(16) __half g_xFrag[8 * 256 * A_CH_HALF];    // [mtile][t][frag]
__device__ __align__(16) __half g_pFrag[8 * A_CH_HALF];          // [mtile][frag]
__device__ __align__(16) __half g_WFrag[NCHK * 16 * W_CH_HALF];  // [kc][utile][frag]

// ---------------- helpers ----------------
__device__ __forceinline__ void mma_f16(float (&d)[4], const uint32_t (&a)[4],
                                        uint32_t b0, uint32_t b1) {
    asm volatile(
        "mma.sync.aligned.m16n8k16.row.col.f32.f16.f16.f32 "
        "{%0,%1,%2,%3}, {%4,%5,%6,%7}, {%8,%9}, {%0,%1,%2,%3};\n"
        : "+f"(d[0]), "+f"(d[1]), "+f"(d[2]), "+f"(d[3])
        : "r"(a[0]), "r"(a[1]), "r"(a[2]), "r"(a[3]), "r"(b0), "r"(b1));
}
// fast gates: __expf-based (MUFU), rel err ~1e-6, overflow-safe forms
__device__ __forceinline__ float fsigm(float x) {
    return 1.0f / (1.0f + __expf(-x));
}
__device__ __forceinline__ float ftanh(float x) {
    float e = __expf(2.0f * x);                    // e->inf: 1 ; e->0: -1
    return 1.0f - __fdividef(2.0f, e + 1.0f);
}

__device__ __forceinline__ void mbar_init(uint32_t mbar, uint32_t count) {
    asm volatile("mbarrier.init.shared.b64 [%0], %1;" :: "r"(mbar), "r"(count) : "memory");
}
__device__ __forceinline__ void mbar_expect_tx(uint32_t mbar, uint32_t bytes) {
    asm volatile("mbarrier.arrive.expect_tx.shared.b64 _, [%0], %1;"
                 :: "r"(mbar), "r"(bytes) : "memory");
}
__device__ __forceinline__ void mbar_wait(uint32_t mbar, uint32_t parity) {
    asm volatile(
        "{\n\t.reg .pred P;\n\t"
        "W%=:\n\t"
        "mbarrier.try_wait.parity.acquire.cta.shared::cta.b64 P, [%0], %1, 0x989680;\n\t"
        "@P bra.uni D%=;\n\t"
        "bra.uni W%=;\n\t"
        "D%=:\n\t}"
        :: "r"(mbar), "r"(parity) : "memory");
}
// 1-D bulk async copy global->shared, completion via mbarrier tx-bytes (sm_90+)
__device__ __forceinline__ void bulk_cp(uint32_t dst, const void* src, uint32_t bytes,
                                        uint32_t mbar) {
    asm volatile(
        "cp.async.bulk.shared::cluster.global.mbarrier::complete_tx::bytes [%0], [%1], %2, [%3];"
        :: "r"(dst), "l"(src), "r"(bytes), "r"(mbar) : "memory");
}

// half index of A-side element (m in [0,128), k in [0,64)) within a chunk image
__device__ __forceinline__ int a_frag_hidx(int m, int k) {
    int ks = k >> 4, kin = k & 15;
    int khi = kin >> 3, tigk = (kin & 7) >> 1, hsel = kin & 1;
    int m16 = m >> 4, r16 = m & 15, gid = r16 & 7, rhi = r16 >> 3;
    int lane = gid * 4 + tigk;
    int q = khi * 2 + rhi;
    return ((((ks * 8 + m16) * 32) + lane) * 4 + q) * 2 + hsel;
}

// ---------------- prep kernels (once per launch) ----------------
__global__ void init_state_kernel() {
    int i = blockIdx.x * blockDim.x + threadIdx.x;
    if (i < B_SZ * U_SZ) g_c[i] = 0.0f;
    if (i < 8 * 16 * A_CH_HALF) g_hFrag[0][i] = __float2half(0.0f);
}

__global__ void prep_x_kernel(const float* __restrict__ x) {
    int i = blockIdx.x * blockDim.x + threadIdx.x;   // over B*T*I
    if (i >= B_SZ * T_SZ * I_SZ) return;
    int col = i & 63, t = (i >> 6) & 255, row = i >> 14;
    int mtile = row >> 7, m = row & 127;
    g_xFrag[((size_t)mtile * 256 + t) * A_CH_HALF + a_frag_hidx(m, col)] = __float2half_rn(x[i]);
}

__global__ void prep_w_kernel(const float* __restrict__ Wk, const float* __restrict__ Wr) {
    int i = blockIdx.x * blockDim.x + threadIdx.x;   // over NCHK*16*W_CH_HALF
    if (i >= NCHK * 16 * W_CH_HALF) return;
    int hsel  = i & 1;
    int jp    = (i >> 1) & 3;
    int lane  = (i >> 3) & 31;
    int nbp   = (i >> 8) & 15;
    int ks    = (i >> 12) & 3;
    int utile = (i >> 14) & 15;
    int kc    = i >> 18;
    int gid = lane >> 2, tigk = lane & 3;
    int n8 = nbp * 2 + (jp >> 1);
    int bhi = jp & 1;
    int n_local = n8 * 8 + gid;                        // 0..255 = 4*u_local + gate
    int ul = n_local >> 2, gate = n_local & 3;
    int colW = gate * U_SZ + utile * UN + ul;
    int kg = kc * KC + ks * 16 + bhi * 8 + tigk * 2 + hsel;
    float v = (kg < I_SZ) ? Wk[(size_t)kg * 4096 + colW]
                          : Wr[(size_t)(kg - I_SZ) * 4096 + colW];
    g_WFrag[i] = __float2half_rn(v);
}

// ---------------- LSTM step (TMA bulk copies, mbarrier pipeline) ----------------
__global__ __launch_bounds__(NTHR, 1)
void lstm_step_kernel(int t, int par, int use_pred, const float* __restrict__ bias) {
    extern __shared__ uint32_t smu[];
    __shared__ __align__(8) uint64_t mbars[NSTAGE];

    uint32_t smb;
    asm("{ .reg .u64 t; cvta.to.shared.u64 t, %1; cvt.u32.u64 %0, t; }" : "=r"(smb) : "l"(smu));
    uint32_t mb0;
    asm("{ .reg .u64 t; cvta.to.shared.u64 t, %1; cvt.u32.u64 %0, t; }" : "=r"(mb0) : "l"(mbars));

    const int tid  = threadIdx.x;
    const int lane = tid & 31;
    const int wid  = tid >> 5;        // 0..15
    const int gid  = lane >> 2;
    const int tig  = lane & 3;

    const int utile = blockIdx.x & 15;
    const int mtile = blockIdx.x >> 4;
    const int u0 = utile * UN;
    const int m0 = mtile * BM;

    const int wmi = wid >> 2;         // M warp 0..3
    const int wni = wid & 3;          // N warp 0..3
    const int wm0 = wmi * 32;
    const int wn0 = wni * 64;
    const int m16b = wmi * 2;         // A m16 base (+mt in 0..1)
    const int nbpb = wni * 4;         // W nbp base (+ntp in 0..3)

    if (tid == 0) {
#pragma unroll
        for (int s = 0; s < NSTAGE; s++) mbar_init(mb0 + s * 8, 1);
    }
    __syncthreads();

    auto issue = [&](int ch) {
        uint32_t mbar = mb0 + (uint32_t)(ch & 3) * 8u;
        uint32_t stg  = smb + (uint32_t)(ch & 3) * STAGE_BYTES;
        const void* a;
        if (ch == 0) {
            a = use_pred ? (const void*)(g_pFrag + (size_t)mtile * A_CH_HALF)
                         : (const void*)(g_xFrag + ((size_t)mtile * 256 + t) * A_CH_HALF);
        } else {
            a = (const void*)(g_hFrag[par] + ((size_t)mtile * 16 + (ch - 1)) * A_CH_HALF);
        }
        const void* w = (const void*)(g_WFrag + ((size_t)ch * 16 + utile) * W_CH_HALF);
        mbar_expect_tx(mbar, STAGE_BYTES);
        bulk_cp(stg, a, A_BYTES, mbar);
        bulk_cp(stg + A_BYTES, w, W_BYTES, mbar);
    };

    float acc[2][8][4];
#pragma unroll
    for (int mt = 0; mt < 2; mt++)
#pragma unroll
        for (int nt = 0; nt < 8; nt++)
#pragma unroll
            for (int q = 0; q < 4; q++) acc[mt][nt][q] = 0.0f;

    if (tid == 0) { issue(0); issue(1); issue(2); }

    for (int ch = 0; ch < NCHK; ch++) {
        mbar_wait(mb0 + (uint32_t)(ch & 3) * 8u, (uint32_t)((ch >> 2) & 1));
        __syncthreads();
        if (tid == 0 && ch + 3 < NCHK) issue(ch + 3);

        const uint32_t* as = smu + (ch & 3) * STAGE_U32;
        const uint32_t* ws = as + A_CH_U32;

#pragma unroll
        for (int ks = 0; ks < 4; ks++) {
            uint4 a_f[2], b_f[4];
#pragma unroll
            for (int mt = 0; mt < 2; mt++)
                a_f[mt] = *(const uint4*)(as + (((ks * 8 + m16b + mt) * 32) + lane) * 4);
#pragma unroll
            for (int ntp = 0; ntp < 4; ntp++)
                b_f[ntp] = *(const uint4*)(ws + (((ks * 16 + nbpb + ntp) * 32) + lane) * 4);

#pragma unroll
            for (int ntp = 0; ntp < 4; ntp++) {
#pragma unroll
                for (int mt = 0; mt < 2; mt++) {
                    uint32_t af[4] = { a_f[mt].x, a_f[mt].y, a_f[mt].z, a_f[mt].w };
                    mma_f16(acc[mt][2 * ntp],     af, b_f[ntp].x, b_f[ntp].y);
                    mma_f16(acc[mt][2 * ntp + 1], af, b_f[ntp].z, b_f[ntp].w);
                }
            }
        }
    }

    // ---- epilogue (R13 structure, fast gates): both lanes compute, !pg stores ----
    const int pg = tig & 1;
    float*  hl = g_h[par ^ 1];
    __half* hf = g_hFrag[par ^ 1] + ((size_t)mtile * 16 + utile) * A_CH_HALF;
#pragma unroll
    for (int mt = 0; mt < 2; mt++) {
        const int r1 = m0 + wm0 + mt * 16 + gid;
        const int m16 = m16b + mt;
#pragma unroll
        for (int nt = 0; nt < 8; nt++) {
            float c0 = acc[mt][nt][0], c1 = acc[mt][nt][1];
            float c2 = acc[mt][nt][2], c3 = acc[mt][nt][3];
            const int col  = wn0 + nt * 8 + 2 * tig;
            const int unit = u0 + (col >> 2);
            const float ba0 = pg ? __ldg(bias + 2 * U_SZ + unit) : __ldg(bias + unit);
            const float ba1 = pg ? __ldg(bias + 3 * U_SZ + unit) : __ldg(bias + U_SZ + unit);
            c0 += ba0; c1 += ba1; c2 += ba0; c3 += ba1;

            float s0 = __shfl_xor_sync(0xffffffffu, c0, 1);
            float s1 = __shfl_xor_sync(0xffffffffu, c1, 1);
            float s2 = __shfl_xor_sync(0xffffffffu, c2, 1);
            float s3 = __shfl_xor_sync(0xffffffffu, c3, 1);

            const int ul2  = unit & 63;
            const int ks2  = ul2 >> 4, kin = ul2 & 15;
            const int khi2 = kin >> 3, tig2 = (kin & 7) >> 1, hsel = kin & 1;
            const int lane2 = gid * 4 + tig2;

            {   // row r1 (rhi = 0)
                float gi = pg ? s0 : c0, gf = pg ? s1 : c1;
                float gg = pg ? c0 : s0, go = pg ? c1 : s1;
                int idx = r1 * U_SZ + unit;
                float cold = g_c[idx];
                float cn = fsigm(gf) * cold + fsigm(gi) * ftanh(gg);
                float hv = fsigm(go) * ftanh(cn);
                if (!pg) {
                    g_c[idx] = cn; hl[idx] = hv;
                    int q = khi2 * 2 + 0;
                    hf[((((ks2 * 8 + m16) * 32) + lane2) * 4 + q) * 2 + hsel] = __float2half_rn(hv);
                }
            }
            {   // row r1 + 8 (rhi = 1)
                float gi = pg ? s2 : c2, gf = pg ? s3 : c3;
                float gg = pg ? c2 : s2, go = pg ? c3 : s3;
                int idx = (r1 + 8) * U_SZ + unit;
                float cold = g_c[idx];
                float cn = fsigm(gf) * cold + fsigm(gi) * ftanh(gg);
                float hv = fsigm(go) * ftanh(cn);
                if (!pg) {
                    g_c[idx] = cn; hl[idx] = hv;
                    int q = khi2 * 2 + 1;
                    hf[((((ks2 * 8 + m16) * 32) + lane2) * 4 + q) * 2 + hsel] = __float2half_rn(hv);
                }
            }
        }
    }
}

// ---------------- dense head ----------------
__global__ __launch_bounds__(256)
void dense_head_kernel(int par, const float* __restrict__ Wd, const float* __restrict__ bd,
                       const int* __restrict__ oidx, int n_idx,
                       float* __restrict__ out, int s, int S) {
    __shared__ float hs[8 * U_SZ];
    const int tid = threadIdx.x;
    const int r0 = blockIdx.x * 8;
    const float* h = g_h[par];
    for (int i = tid; i < 8 * U_SZ; i += 256)
        hs[i] = h[(size_t)(r0 + (i >> 10)) * U_SZ + (i & 1023)];
    __syncthreads();

    const int icol = tid & 63;
    const int rr = tid >> 6;
#pragma unroll
    for (int rp = 0; rp < 2; rp++) {
        const int r = rr + rp * 4;
        const float* hrow = hs + r * U_SZ;
        float a0 = 0.f, a1 = 0.f, a2 = 0.f, a3 = 0.f;
#pragma unroll 4
        for (int u = 0; u < U_SZ; u += 4) {
            a0 += hrow[u]     * __ldg(Wd + (size_t)u * I_SZ + icol);
            a1 += hrow[u + 1] * __ldg(Wd + (size_t)(u + 1) * I_SZ + icol);
            a2 += hrow[u + 2] * __ldg(Wd + (size_t)(u + 2) * I_SZ + icol);
            a3 += hrow[u + 3] * __ldg(Wd + (size_t)(u + 3) * I_SZ + icol);
        }
        float acc = __ldg(bd + icol) + (a0 + a1) + (a2 + a3);
        const int gb = r0 + r;
        int mtile = gb >> 7, m = gb & 127;
        g_pFrag[(size_t)mtile * A_CH_HALF + a_frag_hidx(m, icol)] = __float2half_rn(acc);
        for (int j = 0; j < n_idx; j++)
            if (__ldg(oidx + j) == icol)
                out[(size_t)gb * S * n_idx + s * n_idx + j] = acc;
    }
}

// ---------------- launch ----------------
extern "C" void kernel_launch(void* const* d_in, const int* in_sizes, int n_in,
                              void* d_out, int out_size) {
    const float* inputs = (const float*)d_in[0];
    const float* Wk     = (const float*)d_in[1];
    const float* Wr     = (const float*)d_in[2];
    const float* bias   = (const float*)d_in[3];
    const float* Wd     = (const float*)d_in[4];
    const float* bd     = (const float*)d_in[5];
    const int*   oidx   = (const int*)d_in[6];
    float*       out    = (float*)d_out;

    const int T     = in_sizes[0] / (B_SZ * I_SZ);   // 256
    const int n_idx = in_sizes[6];                   // 2
    const int S     = out_size / (B_SZ * n_idx);     // 64

    cudaFuncSetAttribute(lstm_step_kernel,
                         cudaFuncAttributeMaxDynamicSharedMemorySize, SMEM_BYTES);

    init_state_kernel<<<(B_SZ * U_SZ + 255) / 256, 256>>>();
    prep_x_kernel<<<(B_SZ * T_SZ * I_SZ + 255) / 256, 256>>>(inputs);
    prep_w_kernel<<<(NCHK * 16 * W_CH_HALF + 255) / 256, 256>>>(Wk, Wr);

    int par = 0;
    for (int t = 0; t < T; t++) {
        lstm_step_kernel<<<128, NTHR, SMEM_BYTES>>>(t, par, 0, bias);
        par ^= 1;
    }
    dense_head_kernel<<<128, 256>>>(par, Wd, bd, oidx, n_idx, out, 0, S);
    for (int s = 1; s < S; s++) {
        lstm_step_kernel<<<128, NTHR, SMEM_BYTES>>>(0, par, 1, bias);
        par ^= 1;
        dense_head_kernel<<<128, 256>>>(par, Wd, bd, oidx, n_idx, out, s, S);
    }
}

// round 17
// speedup vs baseline: 1.2918x; 1.0339x over previous
#include <cuda_runtime.h>
#include <cuda_fp16.h>
#include <cstdint>

// Shapes (specialized)
#define B_SZ   1024
#define I_SZ   64
#define U_SZ   1024
#define T_SZ   256
#define KC     64          // K per chunk
#define NCHK   17          // (64+1024)/64
#define BM     128
#define BN     128         // 32 units x 4 gates (col = 4*u_local + gate)
#define UN     32
#define NUTIL  32
#define NTHR   256         // 8 warps: 4 in M x 2 in N, warp tile 32x64

// fp16 fragment-major chunk images (m16n8k16):
//  A chunk: [ks(4)][m16(8)][lane(32)][q(4)] u32 = 4096 u32 = 16KB
//  W chunk: [ks(4)][nbp(8)][lane(32)][jp(4)] u32 = 4096 u32 = 16KB (BN=128)
#define A_CH_U32  4096
#define W_CH_U32  4096
#define A_CH_HALF (A_CH_U32 * 2)
#define W_CH_HALF (W_CH_U32 * 2)
#define A_BYTES   (A_CH_U32 * 4)               // 16384
#define W_BYTES   (W_CH_U32 * 4)               // 16384
#define STAGE_U32 (A_CH_U32 + W_CH_U32)        // 8192 u32 = 32KB
#define STAGE_BYTES (STAGE_U32 * 4)
#define NSTAGE    3
#define SMEM_BYTES (NSTAGE * STAGE_BYTES)      // 96KB dynamic -> 2 CTAs/SM

// ---------------- device state ----------------
__device__ float  g_h[2][B_SZ * U_SZ];                           // linear h (dense head)
__device__ float  g_c[B_SZ * U_SZ];
__device__ __align__(16) __half g_hFrag[2][8 * 16 * A_CH_HALF];  // [par][mtile][hchunk][frag]
__device__ __align__(16) __half g_xFrag[8 * 256 * A_CH_HALF];    // [mtile][t][frag]
__device__ __align__(16) __half g_pFrag[8 * A_CH_HALF];          // [mtile][frag]
__device__ __align__(16) __half g_WFrag[NCHK * NUTIL * W_CH_HALF]; // [kc][utile][frag]

// ---------------- helpers ----------------
__device__ __forceinline__ void mma_f16(float (&d)[4], const uint32_t (&a)[4],
                                        uint32_t b0, uint32_t b1) {
    asm volatile(
        "mma.sync.aligned.m16n8k16.row.col.f32.f16.f16.f32 "
        "{%0,%1,%2,%3}, {%4,%5,%6,%7}, {%8,%9}, {%0,%1,%2,%3};\n"
        : "+f"(d[0]), "+f"(d[1]), "+f"(d[2]), "+f"(d[3])
        : "r"(a[0]), "r"(a[1]), "r"(a[2]), "r"(a[3]), "r"(b0), "r"(b1));
}
// fast gates: __expf-based (MUFU), rel err ~1e-6, overflow-safe forms
__device__ __forceinline__ float fsigm(float x) {
    return 1.0f / (1.0f + __expf(-x));
}
__device__ __forceinline__ float ftanh(float x) {
    float e = __expf(2.0f * x);                    // e->inf: 1 ; e->0: -1
    return 1.0f - __fdividef(2.0f, e + 1.0f);
}

__device__ __forceinline__ void mbar_init(uint32_t mbar, uint32_t count) {
    asm volatile("mbarrier.init.shared.b64 [%0], %1;" :: "r"(mbar), "r"(count) : "memory");
}
__device__ __forceinline__ void mbar_expect_tx(uint32_t mbar, uint32_t bytes) {
    asm volatile("mbarrier.arrive.expect_tx.shared.b64 _, [%0], %1;"
                 :: "r"(mbar), "r"(bytes) : "memory");
}
__device__ __forceinline__ void mbar_wait(uint32_t mbar, uint32_t parity) {
    asm volatile(
        "{\n\t.reg .pred P;\n\t"
        "W%=:\n\t"
        "mbarrier.try_wait.parity.acquire.cta.shared::cta.b64 P, [%0], %1, 0x989680;\n\t"
        "@P bra.uni D%=;\n\t"
        "bra.uni W%=;\n\t"
        "D%=:\n\t}"
        :: "r"(mbar), "r"(parity) : "memory");
}
// 1-D bulk async copy global->shared, completion via mbarrier tx-bytes (sm_90+)
__device__ __forceinline__ void bulk_cp(uint32_t dst, const void* src, uint32_t bytes,
                                        uint32_t mbar) {
    asm volatile(
        "cp.async.bulk.shared::cluster.global.mbarrier::complete_tx::bytes [%0], [%1], %2, [%3];"
        :: "r"(dst), "l"(src), "r"(bytes), "r"(mbar) : "memory");
}

// half index of A-side element (m in [0,128), k in [0,64)) within a chunk image
__device__ __forceinline__ int a_frag_hidx(int m, int k) {
    int ks = k >> 4, kin = k & 15;
    int khi = kin >> 3, tigk = (kin & 7) >> 1, hsel = kin & 1;
    int m16 = m >> 4, r16 = m & 15, gid = r16 & 7, rhi = r16 >> 3;
    int lane = gid * 4 + tigk;
    int q = khi * 2 + rhi;
    return ((((ks * 8 + m16) * 32) + lane) * 4 + q) * 2 + hsel;
}

// ---------------- prep kernels (once per launch) ----------------
__global__ void init_state_kernel() {
    int i = blockIdx.x * blockDim.x + threadIdx.x;
    if (i < B_SZ * U_SZ) g_c[i] = 0.0f;
    if (i < 8 * 16 * A_CH_HALF) g_hFrag[0][i] = __float2half(0.0f);
}

__global__ void prep_x_kernel(const float* __restrict__ x) {
    int i = blockIdx.x * blockDim.x + threadIdx.x;   // over B*T*I
    if (i >= B_SZ * T_SZ * I_SZ) return;
    int col = i & 63, t = (i >> 6) & 255, row = i >> 14;
    int mtile = row >> 7, m = row & 127;
    g_xFrag[((size_t)mtile * 256 + t) * A_CH_HALF + a_frag_hidx(m, col)] = __float2half_rn(x[i]);
}

// W frag for BN=128: [kc][utile(32)][ks(4)][nbp(8)][lane(32)][jp(4)][hsel]
__global__ void prep_w_kernel(const float* __restrict__ Wk, const float* __restrict__ Wr) {
    int i = blockIdx.x * blockDim.x + threadIdx.x;   // over NCHK*NUTIL*W_CH_HALF
    if (i >= NCHK * NUTIL * W_CH_HALF) return;
    int hsel  = i & 1;
    int jp    = (i >> 1) & 3;
    int lane  = (i >> 3) & 31;
    int nbp   = (i >> 8) & 7;          // 8 n-tile pairs (BN=128)
    int ks    = (i >> 11) & 3;
    int utile = (i >> 13) & 31;        // W_CH_HALF = 2^13
    int kc    = i >> 18;               // 32 * 2^13 = 2^18 per kc
    int gid = lane >> 2, tigk = lane & 3;
    int n8 = nbp * 2 + (jp >> 1);
    int bhi = jp & 1;
    int n_local = n8 * 8 + gid;                        // 0..127 = 4*u_local + gate
    int ul = n_local >> 2, gate = n_local & 3;
    int colW = gate * U_SZ + utile * UN + ul;
    int kg = kc * KC + ks * 16 + bhi * 8 + tigk * 2 + hsel;
    float v = (kg < I_SZ) ? Wk[(size_t)kg * 4096 + colW]
                          : Wr[(size_t)(kg - I_SZ) * 4096 + colW];
    g_WFrag[i] = __float2half_rn(v);
}

// ---------------- LSTM step (256 thr, BN=128, 3-stage TMA ring, 2 CTAs/SM) ----------
__global__ __launch_bounds__(NTHR, 2)
void lstm_step_kernel(int t, int par, int use_pred, const float* __restrict__ bias) {
    extern __shared__ uint32_t smu[];
    __shared__ __align__(8) uint64_t mbars[NSTAGE];

    uint32_t smb;
    asm("{ .reg .u64 t; cvta.to.shared.u64 t, %1; cvt.u32.u64 %0, t; }" : "=r"(smb) : "l"(smu));
    uint32_t mb0;
    asm("{ .reg .u64 t; cvta.to.shared.u64 t, %1; cvt.u32.u64 %0, t; }" : "=r"(mb0) : "l"(mbars));

    const int tid  = threadIdx.x;
    const int lane = tid & 31;
    const int wid  = tid >> 5;        // 0..7
    const int gid  = lane >> 2;
    const int tig  = lane & 3;

    const int utile = blockIdx.x & 31;
    const int mtile = blockIdx.x >> 5;
    const int u0 = utile * UN;
    const int m0 = mtile * BM;

    const int wmi = wid >> 1;         // M warp 0..3
    const int wni = wid & 1;          // N warp 0..1
    const int wm0 = wmi * 32;
    const int wn0 = wni * 64;
    const int m16b = wmi * 2;         // A m16 base (+mt in 0..1)
    const int nbpb = wni * 4;         // W nbp base (+ntp in 0..3)

    if (tid == 0) {
#pragma unroll
        for (int s = 0; s < NSTAGE; s++) mbar_init(mb0 + s * 8, 1);
    }
    __syncthreads();

    // issue chunk ch into explicit stage slot
    auto issue = [&](int ch, int stg_idx) {
        uint32_t mbar = mb0 + (uint32_t)stg_idx * 8u;
        uint32_t stg  = smb + (uint32_t)stg_idx * STAGE_BYTES;
        const void* a;
        if (ch == 0) {
            a = use_pred ? (const void*)(g_pFrag + (size_t)mtile * A_CH_HALF)
                         : (const void*)(g_xFrag + ((size_t)mtile * 256 + t) * A_CH_HALF);
        } else {
            a = (const void*)(g_hFrag[par] + ((size_t)mtile * 16 + (ch - 1)) * A_CH_HALF);
        }
        const void* w = (const void*)(g_WFrag + ((size_t)ch * NUTIL + utile) * W_CH_HALF);
        mbar_expect_tx(mbar, STAGE_BYTES);
        bulk_cp(stg, a, A_BYTES, mbar);
        bulk_cp(stg + A_BYTES, w, W_BYTES, mbar);
    };

    float acc[2][8][4];
#pragma unroll
    for (int mt = 0; mt < 2; mt++)
#pragma unroll
        for (int nt = 0; nt < 8; nt++)
#pragma unroll
            for (int q = 0; q < 4; q++) acc[mt][nt][q] = 0.0f;

    if (tid == 0) { issue(0, 0); issue(1, 1); }

    int stage = 0, phase = 0;
    for (int ch = 0; ch < NCHK; ch++) {
        mbar_wait(mb0 + (uint32_t)stage * 8u, (uint32_t)phase);
        __syncthreads();
        // issue ch+2 into stage (stage+2)%3 == (stage-1)%3: fully read in iter ch-1,
        // and all threads passed this barrier after those reads -> safe.
        if (tid == 0 && ch + 2 < NCHK) {
            int s2 = stage + 2; if (s2 >= NSTAGE) s2 -= NSTAGE;
            issue(ch + 2, s2);
        }

        const uint32_t* as = smu + stage * STAGE_U32;
        const uint32_t* ws = as + A_CH_U32;

#pragma unroll
        for (int ks = 0; ks < 4; ks++) {
            uint4 a_f[2], b_f[4];
#pragma unroll
            for (int mt = 0; mt < 2; mt++)
                a_f[mt] = *(const uint4*)(as + (((ks * 8 + m16b + mt) * 32) + lane) * 4);
#pragma unroll
            for (int ntp = 0; ntp < 4; ntp++)
                b_f[ntp] = *(const uint4*)(ws + (((ks * 8 + nbpb + ntp) * 32) + lane) * 4);

#pragma unroll
            for (int ntp = 0; ntp < 4; ntp++) {
#pragma unroll
                for (int mt = 0; mt < 2; mt++) {
                    uint32_t af[4] = { a_f[mt].x, a_f[mt].y, a_f[mt].z, a_f[mt].w };
                    mma_f16(acc[mt][2 * ntp],     af, b_f[ntp].x, b_f[ntp].y);
                    mma_f16(acc[mt][2 * ntp + 1], af, b_f[ntp].z, b_f[ntp].w);
                }
            }
        }
        if (++stage == NSTAGE) { stage = 0; phase ^= 1; }
    }

    // ---- epilogue (R13/R15 structure): both lanes compute, !pg stores ----
    const int pg = tig & 1;
    float*  hl = g_h[par ^ 1];
    __half* hfb = g_hFrag[par ^ 1];
#pragma unroll
    for (int mt = 0; mt < 2; mt++) {
        const int r1 = m0 + wm0 + mt * 16 + gid;
        const int m16 = m16b + mt;
#pragma unroll
        for (int nt = 0; nt < 8; nt++) {
            float c0 = acc[mt][nt][0], c1 = acc[mt][nt][1];
            float c2 = acc[mt][nt][2], c3 = acc[mt][nt][3];
            const int col  = wn0 + nt * 8 + 2 * tig;
            const int unit = u0 + (col >> 2);
            const float ba0 = pg ? __ldg(bias + 2 * U_SZ + unit) : __ldg(bias + unit);
            const float ba1 = pg ? __ldg(bias + 3 * U_SZ + unit) : __ldg(bias + U_SZ + unit);
            c0 += ba0; c1 += ba1; c2 += ba0; c3 += ba1;

            float s0 = __shfl_xor_sync(0xffffffffu, c0, 1);
            float s1 = __shfl_xor_sync(0xffffffffu, c1, 1);
            float s2 = __shfl_xor_sync(0xffffffffu, c2, 1);
            float s3 = __shfl_xor_sync(0xffffffffu, c3, 1);

            // h frag slot: hchunk = unit>>6, klocal = unit&63
            __half* hf = hfb + ((size_t)mtile * 16 + (unit >> 6)) * A_CH_HALF;
            const int ul2  = unit & 63;
            const int ks2  = ul2 >> 4, kin = ul2 & 15;
            const int khi2 = kin >> 3, tig2 = (kin & 7) >> 1, hsel = kin & 1;
            const int lane2 = gid * 4 + tig2;

            {   // row r1 (rhi = 0)
                float gi = pg ? s0 : c0, gf = pg ? s1 : c1;
                float gg = pg ? c0 : s0, go = pg ? c1 : s1;
                int idx = r1 * U_SZ + unit;
                float cold = g_c[idx];
                float cn = fsigm(gf) * cold + fsigm(gi) * ftanh(gg);
                float hv = fsigm(go) * ftanh(cn);
                if (!pg) {
                    g_c[idx] = cn; hl[idx] = hv;
                    int q = khi2 * 2 + 0;
                    hf[((((ks2 * 8 + m16) * 32) + lane2) * 4 + q) * 2 + hsel] = __float2half_rn(hv);
                }
            }
            {   // row r1 + 8 (rhi = 1)
                float gi = pg ? s2 : c2, gf = pg ? s3 : c3;
                float gg = pg ? c2 : s2, go = pg ? c3 : s3;
                int idx = (r1 + 8) * U_SZ + unit;
                float cold = g_c[idx];
                float cn = fsigm(gf) * cold + fsigm(gi) * ftanh(gg);
                float hv = fsigm(go) * ftanh(cn);
                if (!pg) {
                    g_c[idx] = cn; hl[idx] = hv;
                    int q = khi2 * 2 + 1;
                    hf[((((ks2 * 8 + m16) * 32) + lane2) * 4 + q) * 2 + hsel] = __float2half_rn(hv);
                }
            }
        }
    }
}

// ---------------- dense head ----------------
__global__ __launch_bounds__(256)
void dense_head_kernel(int par, const float* __restrict__ Wd, const float* __restrict__ bd,
                       const int* __restrict__ oidx, int n_idx,
                       float* __restrict__ out, int s, int S) {
    __shared__ float hs[8 * U_SZ];
    const int tid = threadIdx.x;
    const int r0 = blockIdx.x * 8;
    const float* h = g_h[par];
    for (int i = tid; i < 8 * U_SZ; i += 256)
        hs[i] = h[(size_t)(r0 + (i >> 10)) * U_SZ + (i & 1023)];
    __syncthreads();

    const int icol = tid & 63;
    const int rr = tid >> 6;
#pragma unroll
    for (int rp = 0; rp < 2; rp++) {
        const int r = rr + rp * 4;
        const float* hrow = hs + r * U_SZ;
        float a0 = 0.f, a1 = 0.f, a2 = 0.f, a3 = 0.f;
#pragma unroll 4
        for (int u = 0; u < U_SZ; u += 4) {
            a0 += hrow[u]     * __ldg(Wd + (size_t)u * I_SZ + icol);
            a1 += hrow[u + 1] * __ldg(Wd + (size_t)(u + 1) * I_SZ + icol);
            a2 += hrow[u + 2] * __ldg(Wd + (size_t)(u + 2) * I_SZ + icol);
            a3 += hrow[u + 3] * __ldg(Wd + (size_t)(u + 3) * I_SZ + icol);
        }
        float acc = __ldg(bd + icol) + (a0 + a1) + (a2 + a3);
        const int gb = r0 + r;
        int mtile = gb >> 7, m = gb & 127;
        g_pFrag[(size_t)mtile * A_CH_HALF + a_frag_hidx(m, icol)] = __float2half_rn(acc);
        for (int j = 0; j < n_idx; j++)
            if (__ldg(oidx + j) == icol)
                out[(size_t)gb * S * n_idx + s * n_idx + j] = acc;
    }
}

// ---------------- launch ----------------
extern "C" void kernel_launch(void* const* d_in, const int* in_sizes, int n_in,
                              void* d_out, int out_size) {
    const float* inputs = (const float*)d_in[0];
    const float* Wk     = (const float*)d_in[1];
    const float* Wr     = (const float*)d_in[2];
    const float* bias   = (const float*)d_in[3];
    const float* Wd     = (const float*)d_in[4];
    const float* bd     = (const float*)d_in[5];
    const int*   oidx   = (const int*)d_in[6];
    float*       out    = (float*)d_out;

    const int T     = in_sizes[0] / (B_SZ * I_SZ);   // 256
    const int n_idx = in_sizes[6];                   // 2
    const int S     = out_size / (B_SZ * n_idx);     // 64

    cudaFuncSetAttribute(lstm_step_kernel,
                         cudaFuncAttributeMaxDynamicSharedMemorySize, SMEM_BYTES);

    init_state_kernel<<<(B_SZ * U_SZ + 255) / 256, 256>>>();
    prep_x_kernel<<<(B_SZ * T_SZ * I_SZ + 255) / 256, 256>>>(inputs);
    prep_w_kernel<<<(NCHK * NUTIL * W_CH_HALF + 255) / 256, 256>>>(Wk, Wr);

    int par = 0;
    for (int t = 0; t < T; t++) {
        lstm_step_kernel<<<256, NTHR, SMEM_BYTES>>>(t, par, 0, bias);
        par ^= 1;
    }
    dense_head_kernel<<<128, 256>>>(par, Wd, bd, oidx, n_idx, out, 0, S);
    for (int s = 1; s < S; s++) {
        lstm_step_kernel<<<256, NTHR, SMEM_BYTES>>>(0, par, 1, bias);
        par ^= 1;
        dense_head_kernel<<<128, 256>>>(par, Wd, bd, oidx, n_idx, out, s, S);
    }
}